// round 13
// baseline (speedup 1.0000x reference)
#include <cuda_runtime.h>
#include <cuda_bf16.h>
#include <cstdint>

#define NG 2048      // genes
#define NC 2048      // cells
#define EK 30720
#define EP 65536
#define NL 4
#define NN (2048*2048)
#define NEG 0.01f

// ---------------- scratch (static device globals; no allocation) -------------
__device__ float g_T[NN];                 // fp32 activations, orientation A
__device__ __nv_bfloat16 g_Thi[NN];
__device__ __nv_bfloat16 g_Tlo[NN];
__device__ float g_U[NN];                 // fp32 activations, orientation B
__device__ __nv_bfloat16 g_Uhi[NN];
__device__ __nv_bfloat16 g_Ulo[NN];
__device__ __nv_bfloat16 g_Mhi[NN];      // mean operand hi/lo
__device__ __nv_bfloat16 g_Mlo[NN];
__device__ __nv_bfloat16 g_Wth[16ll*NN]; // 16 transposed weights, hi
__device__ __nv_bfloat16 g_Wtl[16ll*NN]; // 16 transposed weights, lo

__device__ int   g_cnt_knn[NC];
__device__ int   g_off_knn[NC + 1];
__device__ int   g_cur_knn[NC];
__device__ int   g_src_knn[EK];
__device__ float g_inv_knn[NC];

__device__ int   g_cnt_ppi[NG];
__device__ int   g_off_ppi[NG + 1];
__device__ int   g_cur_ppi[NG];
__device__ int   g_src_ppi[EP];
__device__ float g_inv_ppi[NG];

// ---------------- helpers ------------------------------------------------------
__device__ __forceinline__ uint32_t smem_u32(const void* p) {
    uint32_t a;
    asm("{ .reg .u64 t; cvta.to.shared.u64 t, %1; cvt.u32.u64 %0, t; }" : "=r"(a) : "l"(p));
    return a;
}
#define CP16(dst, src) \
    asm volatile("cp.async.cg.shared.global [%0], [%1], 16;\n" :: "r"(dst), "l"(src))

__device__ __forceinline__ void mma_bf16(float* c, const uint32_t* a, uint32_t b0, uint32_t b1) {
    asm volatile(
        "mma.sync.aligned.m16n8k16.row.col.f32.bf16.bf16.f32 "
        "{%0,%1,%2,%3}, {%4,%5,%6,%7}, {%8,%9}, {%0,%1,%2,%3};\n"
        : "+f"(c[0]), "+f"(c[1]), "+f"(c[2]), "+f"(c[3])
        : "r"(a[0]), "r"(a[1]), "r"(a[2]), "r"(a[3]), "r"(b0), "r"(b1));
}

// ---------------- setup kernels (CSR) ------------------------------------------
__global__ void zero_counts_kernel() {
    int t = blockIdx.x * blockDim.x + threadIdx.x;
    if (t < NC) g_cnt_knn[t] = 0;
    if (t < NG) g_cnt_ppi[t] = 0;
}
__global__ void count_kernel(const int* __restrict__ tgt, int E, int* __restrict__ cnt) {
    int e = blockIdx.x * blockDim.x + threadIdx.x;
    if (e < E) atomicAdd(&cnt[tgt[e]], 1);
}
__global__ void scan_kernel(const int* __restrict__ cnt, int* __restrict__ off,
                            float* __restrict__ inv, int* __restrict__ cur, int n) {
    __shared__ int s[1024];
    int t = threadIdx.x;
    int c0 = cnt[2 * t], c1 = cnt[2 * t + 1];
    s[t] = c0 + c1;
    __syncthreads();
    for (int d = 1; d < 1024; d <<= 1) {
        int v = (t >= d) ? s[t - d] : 0;
        __syncthreads();
        s[t] += v;
        __syncthreads();
    }
    int incl = s[t];
    int ex = incl - (c0 + c1);
    off[2 * t] = ex;       off[2 * t + 1] = ex + c0;
    cur[2 * t] = ex;       cur[2 * t + 1] = ex + c0;
    inv[2 * t]     = 1.0f / fmaxf((float)c0, 1.0f);
    inv[2 * t + 1] = 1.0f / fmaxf((float)c1, 1.0f);
    if (t == 1023) off[n] = incl;
}
__global__ void fill_kernel(const int* __restrict__ src, const int* __restrict__ tgt,
                            int E, int* __restrict__ cur, int* __restrict__ outsrc) {
    int e = blockIdx.x * blockDim.x + threadIdx.x;
    if (e < E) {
        int p = atomicAdd(&cur[tgt[e]], 1);
        outsrc[p] = src[e];
    }
}
__global__ void sort_buckets_kernel(const int* __restrict__ off, int* __restrict__ srcs, int n) {
    int t = blockIdx.x * blockDim.x + threadIdx.x;
    if (t >= n) return;
    int a = off[t], b = off[t + 1];
    int m = b - a;
    if (m <= 1 || m > 192) return;
    int buf[192];
    for (int i = 0; i < m; i++) buf[i] = srcs[a + i];
    for (int i = 1; i < m; i++) {
        int key = buf[i];
        int j = i - 1;
        while (j >= 0 && buf[j] > key) { buf[j + 1] = buf[j]; j--; }
        buf[j + 1] = key;
    }
    for (int i = 0; i < m; i++) srcs[a + i] = buf[i];
}

// ---------------- weight prep: transpose + bf16 hi/lo split --------------------
__global__ void wprep_kernel(const float* __restrict__ cWl, const float* __restrict__ cWr,
                             const float* __restrict__ rWl, const float* __restrict__ rWr,
                             __nv_bfloat16* __restrict__ wh, __nv_bfloat16* __restrict__ wl) {
    int z = blockIdx.z;
    const float* src;
    int t = z >> 2;
    if (t == 0) src = cWl; else if (t == 1) src = cWr; else if (t == 2) src = rWl; else src = rWr;
    src += (long)(z & 3) * NN;
    __nv_bfloat16* oh = wh + (long)z * NN;
    __nv_bfloat16* ol = wl + (long)z * NN;

    __shared__ float tile[32][33];
    int x = blockIdx.x * 32 + threadIdx.x;  // n
    int y = blockIdx.y * 32 + threadIdx.y;  // k
#pragma unroll
    for (int i = 0; i < 32; i += 8)
        tile[threadIdx.y + i][threadIdx.x] = src[(long)(y + i) * 2048 + x];
    __syncthreads();
    x = blockIdx.y * 32 + threadIdx.x;      // k
    y = blockIdx.x * 32 + threadIdx.y;      // n
#pragma unroll
    for (int i = 0; i < 32; i += 8) {
        float v = tile[threadIdx.x][threadIdx.y + i];
        long o = (long)(y + i) * 2048 + x;
        __nv_bfloat16 h = __float2bfloat16(v);
        oh[o] = h;
        ol[o] = __float2bfloat16(v - __bfloat162float(h));
    }
}

// ---------------- transpose + hi/lo convert (input x only) ---------------------
__global__ void transpose_conv_kernel(const float* __restrict__ in, float* __restrict__ outf,
                                      __nv_bfloat16* __restrict__ oh, __nv_bfloat16* __restrict__ ol) {
    __shared__ float tile[32][33];
    int x = blockIdx.x * 32 + threadIdx.x;
    int y = blockIdx.y * 32 + threadIdx.y;
#pragma unroll
    for (int i = 0; i < 32; i += 8)
        tile[threadIdx.y + i][threadIdx.x] = in[(long)(y + i) * 2048 + x];
    __syncthreads();
    x = blockIdx.y * 32 + threadIdx.x;
    y = blockIdx.x * 32 + threadIdx.y;
#pragma unroll
    for (int i = 0; i < 32; i += 8) {
        float v = tile[threadIdx.x][threadIdx.y + i];
        long o = (long)(y + i) * 2048 + x;
        outf[o] = v;
        __nv_bfloat16 h = __float2bfloat16(v);
        oh[o] = h;
        ol[o] = __float2bfloat16(v - __bfloat162float(h));
    }
}

// ---------------- segment mean + hi/lo convert ----------------------------------
__device__ __forceinline__ void st_hl(__nv_bfloat162* oh, __nv_bfloat162* ol,
                                      long i2, float x, float y) {
    __nv_bfloat16 hx = __float2bfloat16(x), hy = __float2bfloat16(y);
    oh[i2] = __halves2bfloat162(hx, hy);
    ol[i2] = __halves2bfloat162(__float2bfloat16(x - __bfloat162float(hx)),
                                __float2bfloat16(y - __bfloat162float(hy)));
}
__global__ void agg_conv_kernel(const float* __restrict__ in,
                                __nv_bfloat16* __restrict__ ohr, __nv_bfloat16* __restrict__ olr,
                                const int* __restrict__ off, const int* __restrict__ srcs,
                                const float* __restrict__ inv) {
    int r = blockIdx.x;
    int t = threadIdx.x;
    const float4* base = (const float4*)in;
    float4 a0 = make_float4(0.f, 0.f, 0.f, 0.f), a1 = a0, a2 = a0, a3 = a0;
    int s0 = off[r], s1 = off[r + 1];
    for (int j = s0; j < s1; j++) {
        const float4* row = base + (long)srcs[j] * 512;
        float4 v0 = row[t], v1 = row[t + 128], v2 = row[t + 256], v3 = row[t + 384];
        a0.x += v0.x; a0.y += v0.y; a0.z += v0.z; a0.w += v0.w;
        a1.x += v1.x; a1.y += v1.y; a1.z += v1.z; a1.w += v1.w;
        a2.x += v2.x; a2.y += v2.y; a2.z += v2.z; a2.w += v2.w;
        a3.x += v3.x; a3.y += v3.y; a3.z += v3.z; a3.w += v3.w;
    }
    float sc = inv[r];
    a0.x *= sc; a0.y *= sc; a0.z *= sc; a0.w *= sc;
    a1.x *= sc; a1.y *= sc; a1.z *= sc; a1.w *= sc;
    a2.x *= sc; a2.y *= sc; a2.z *= sc; a2.w *= sc;
    a3.x *= sc; a3.y *= sc; a3.z *= sc; a3.w *= sc;
    __nv_bfloat162* oh = (__nv_bfloat162*)ohr;
    __nv_bfloat162* ol = (__nv_bfloat162*)olr;
    long b2 = (long)r * 1024;
    st_hl(oh, ol, b2 + 2 * (t)       + 0, a0.x, a0.y); st_hl(oh, ol, b2 + 2 * (t)       + 1, a0.z, a0.w);
    st_hl(oh, ol, b2 + 2 * (t + 128) + 0, a1.x, a1.y); st_hl(oh, ol, b2 + 2 * (t + 128) + 1, a1.z, a1.w);
    st_hl(oh, ol, b2 + 2 * (t + 256) + 0, a2.x, a2.y); st_hl(oh, ol, b2 + 2 * (t + 256) + 1, a2.z, a2.w);
    st_hl(oh, ol, b2 + 2 * (t + 384) + 0, a3.x, a3.y); st_hl(oh, ol, b2 + 2 * (t + 384) + 1, a3.z, a3.w);
}

// ---------------- HMMA fused dual GEMM + bias + LeakyReLU ----------------------
// C[m,n] = sum_k A1[m,k]*B1t[n,k] + A2[m,k]*B2t[n,k] + bias[n], lrelu.
// bf16 hi/lo 3-term split, fp32 accum, mma.sync m16n8k16, scalar LDS feeds.
// CTA tile 128x128 (256 CTAs), BK=32, 8 warps (4x2 grid, warp tile 32x64),
// 2-stage cp.async pipeline, TWO CTAs PER SM (occ=2) for latency hiding:
// stage = 40KB, 2 stages = 80KB/CTA, 160KB/SM (< 228KB).
// smem row stride 80B (20 words) => conflict-free LDS fragment access.
// TRANS=1: epilogue stages C tile in smem [n][m], then warp-cooperative
//          coalesced row writes of C^T fp32 + bf16 hi/lo.
// TRANS=0: direct fp32 stores (final layer -> d_out).
#define G_STAGE 40960
#define G_SMEM  (2 * G_STAGE)   // 81920; epilogue staging needs 67584 (fits)

template<int TRANS>
__global__ __launch_bounds__(256, 2)
void gemm_mma_kernel(const __nv_bfloat16* __restrict__ A1h, const __nv_bfloat16* __restrict__ A1l,
                     const __nv_bfloat16* __restrict__ A2h, const __nv_bfloat16* __restrict__ A2l,
                     const __nv_bfloat16* __restrict__ B1h, const __nv_bfloat16* __restrict__ B1l,
                     const __nv_bfloat16* __restrict__ B2h, const __nv_bfloat16* __restrict__ B2l,
                     const float* __restrict__ bias, float* __restrict__ Cf,
                     __nv_bfloat16* __restrict__ CThi, __nv_bfloat16* __restrict__ CTlo) {
    extern __shared__ __align__(16) char smem[];
    const uint32_t sbase = smem_u32(smem);
    const int tid = threadIdx.x;
    const int wid = tid >> 5, lane = tid & 31;
    const int wr = wid >> 1, wc = wid & 1;     // 4x2 warp grid -> 32x64 warp tile
    const int bm = blockIdx.y * 128, bn = blockIdx.x * 128;

    float acc[2][8][4];
#pragma unroll
    for (int i = 0; i < 2; i++)
#pragma unroll
        for (int j = 0; j < 8; j++)
#pragma unroll
            for (int q = 0; q < 4; q++) acc[i][j][q] = 0.f;

    // cp.async assignments: A and B each 512 granules (128 rows x 4 chunks),
    // thread handles granules tid and tid+256 of each.
    const int r0 = tid >> 2,          c0 = tid & 3;
    const int r1 = (tid + 256) >> 2,  c1 = (tid + 256) & 3;

    auto load_stage = [&](int it) {
        const int pr = it >> 6, kc = it & 63;
        const int k0 = kc * 32;
        const uint32_t st = sbase + (it & 1) * G_STAGE;
        const __nv_bfloat16* Ah = pr ? A2h : A1h;
        const __nv_bfloat16* Al = pr ? A2l : A1l;
        const __nv_bfloat16* Bh = pr ? B2h : B1h;
        const __nv_bfloat16* Bl = pr ? B2l : B1l;
        {
            uint32_t so = st + r0 * 80 + c0 * 16;
            long ga = (long)(bm + r0) * 2048 + k0 + c0 * 8;
            long gb = (long)(bn + r0) * 2048 + k0 + c0 * 8;
            CP16(so,          Ah + ga);
            CP16(so + 10240,  Al + ga);
            CP16(so + 20480,  Bh + gb);
            CP16(so + 30720,  Bl + gb);
        }
        {
            uint32_t so = st + r1 * 80 + c1 * 16;
            long ga = (long)(bm + r1) * 2048 + k0 + c1 * 8;
            long gb = (long)(bn + r1) * 2048 + k0 + c1 * 8;
            CP16(so,          Ah + ga);
            CP16(so + 10240,  Al + ga);
            CP16(so + 20480,  Bh + gb);
            CP16(so + 30720,  Bl + gb);
        }
        asm volatile("cp.async.commit_group;\n" ::: "memory");
    };

    load_stage(0);

    for (int it = 0; it < 128; ++it) {
        asm volatile("cp.async.wait_group 0;\n" ::: "memory");  // stage it ready
        __syncthreads();   // publish stage it; all warps done reading the other stage
        if (it + 1 < 128) load_stage(it + 1);

        const char* stp = smem + (it & 1) * G_STAGE;
        const uint32_t* SAh = (const uint32_t*)(stp);
        const uint32_t* SAl = (const uint32_t*)(stp + 10240);
        const uint32_t* SBh = (const uint32_t*)(stp + 20480);
        const uint32_t* SBl = (const uint32_t*)(stp + 30720);

#pragma unroll
        for (int ks = 0; ks < 2; ++ks) {
            const int kw = ks * 8 + (lane & 3);
            uint32_t ah[2][4], al[2][4];
#pragma unroll
            for (int mt = 0; mt < 2; ++mt) {
                const int r = wr * 32 + mt * 16 + (lane >> 2);
                ah[mt][0] = SAh[r * 20 + kw];
                ah[mt][1] = SAh[(r + 8) * 20 + kw];
                ah[mt][2] = SAh[r * 20 + kw + 4];
                ah[mt][3] = SAh[(r + 8) * 20 + kw + 4];
                al[mt][0] = SAl[r * 20 + kw];
                al[mt][1] = SAl[(r + 8) * 20 + kw];
                al[mt][2] = SAl[r * 20 + kw + 4];
                al[mt][3] = SAl[(r + 8) * 20 + kw + 4];
            }
#pragma unroll
            for (int nt = 0; nt < 8; ++nt) {
                const int n = wc * 64 + nt * 8 + (lane >> 2);
                const uint32_t bh0 = SBh[n * 20 + kw];
                const uint32_t bh1 = SBh[n * 20 + kw + 4];
                const uint32_t bl0 = SBl[n * 20 + kw];
                const uint32_t bl1 = SBl[n * 20 + kw + 4];
#pragma unroll
                for (int mt = 0; mt < 2; ++mt) {
                    mma_bf16(acc[mt][nt], ah[mt], bh0, bh1);
                    mma_bf16(acc[mt][nt], ah[mt], bl0, bl1);
                    mma_bf16(acc[mt][nt], al[mt], bh0, bh1);
                }
            }
        }
        __syncthreads();   // all warps done reading stage it before it's overwritten
    }

    if (TRANS) {
        // stage bias+lrelu'd tile into smem as [n][m] (stride 132 words)
        float* sm = (float*)smem;
#pragma unroll
        for (int mt = 0; mt < 2; ++mt) {
            const int m = wr * 32 + mt * 16 + (lane >> 2);
#pragma unroll
            for (int nt = 0; nt < 8; ++nt) {
                const int n = wc * 64 + nt * 8 + 2 * (lane & 3);
                const float b0 = __ldg(bias + bn + n), b1 = __ldg(bias + bn + n + 1);
                float v0 = acc[mt][nt][0] + b0; v0 = (v0 > 0.f) ? v0 : NEG * v0;
                float v1 = acc[mt][nt][1] + b1; v1 = (v1 > 0.f) ? v1 : NEG * v1;
                float v2 = acc[mt][nt][2] + b0; v2 = (v2 > 0.f) ? v2 : NEG * v2;
                float v3 = acc[mt][nt][3] + b1; v3 = (v3 > 0.f) ? v3 : NEG * v3;
                sm[n * 132 + m]           = v0;
                sm[(n + 1) * 132 + m]     = v1;
                sm[n * 132 + m + 8]       = v2;
                sm[(n + 1) * 132 + m + 8] = v3;
            }
        }
        __syncthreads();
        // warp-cooperative coalesced write-out: warp owns rows wid, wid+8, ...
        for (int rr = wid; rr < 128; rr += 8) {
            const float* rowp = sm + rr * 132;
            const long gn = bn + rr;
            float4 v = *(const float4*)(rowp + lane * 4);
            *(float4*)(Cf + gn * 2048 + bm + lane * 4) = v;
            __nv_bfloat16 h0 = __float2bfloat16(v.x), h1 = __float2bfloat16(v.y);
            __nv_bfloat16 h2 = __float2bfloat16(v.z), h3 = __float2bfloat16(v.w);
            __nv_bfloat162 a01 = __halves2bfloat162(h0, h1);
            __nv_bfloat162 a23 = __halves2bfloat162(h2, h3);
            __nv_bfloat162 c01 = __halves2bfloat162(
                __float2bfloat16(v.x - __bfloat162float(h0)),
                __float2bfloat16(v.y - __bfloat162float(h1)));
            __nv_bfloat162 c23 = __halves2bfloat162(
                __float2bfloat16(v.z - __bfloat162float(h2)),
                __float2bfloat16(v.w - __bfloat162float(h3)));
            uint2 uh, ul;
            uh.x = *(uint32_t*)&a01; uh.y = *(uint32_t*)&a23;
            ul.x = *(uint32_t*)&c01; ul.y = *(uint32_t*)&c23;
            *(uint2*)(CThi + gn * 2048 + bm + lane * 4) = uh;
            *(uint2*)(CTlo + gn * 2048 + bm + lane * 4) = ul;
        }
    } else {
        // direct fp32 stores (final layer)
#pragma unroll
        for (int mt = 0; mt < 2; ++mt) {
            const int row = bm + wr * 32 + mt * 16 + (lane >> 2);
#pragma unroll
            for (int nt = 0; nt < 8; ++nt) {
                const int col = bn + wc * 64 + nt * 8 + (lane & 3) * 2;
                const float b0 = __ldg(bias + col), b1 = __ldg(bias + col + 1);
                float v0 = acc[mt][nt][0] + b0;
                float v1 = acc[mt][nt][1] + b1;
                float v2 = acc[mt][nt][2] + b0;
                float v3 = acc[mt][nt][3] + b1;
                float2 o0, o1;
                o0.x = (v0 > 0.f) ? v0 : NEG * v0;
                o0.y = (v1 > 0.f) ? v1 : NEG * v1;
                o1.x = (v2 > 0.f) ? v2 : NEG * v2;
                o1.y = (v3 > 0.f) ? v3 : NEG * v3;
                *(float2*)(Cf + (long)row * 2048 + col) = o0;
                *(float2*)(Cf + (long)(row + 8) * 2048 + col) = o1;
            }
        }
    }
}

// ---------------- launch -----------------------------------------------------
extern "C" void kernel_launch(void* const* d_in, const int* in_sizes, int n_in,
                              void* d_out, int out_size) {
    const float* x      = (const float*)d_in[0];
    const int*   knn    = (const int*)d_in[1];
    const int*   ppi    = (const int*)d_in[2];
    const float* col_Wl = (const float*)d_in[3];
    const float* col_bl = (const float*)d_in[4];
    const float* col_Wr = (const float*)d_in[5];
    const float* row_Wl = (const float*)d_in[6];
    const float* row_bl = (const float*)d_in[7];
    const float* row_Wr = (const float*)d_in[8];

    const int* knn_src = knn;
    const int* knn_tgt = knn + EK;
    const int* ppi_src = ppi;
    const int* ppi_tgt = ppi + EP;

    void *pT_, *pThi_, *pTlo_, *pU_, *pUhi_, *pUlo_, *pMhi_, *pMlo_, *pWh_, *pWl_;
    void *pcK, *poK, *puK, *psK, *piK;
    void *pcP, *poP, *puP, *psP, *piP;
    cudaGetSymbolAddress(&pT_, g_T);
    cudaGetSymbolAddress(&pThi_, g_Thi);
    cudaGetSymbolAddress(&pTlo_, g_Tlo);
    cudaGetSymbolAddress(&pU_, g_U);
    cudaGetSymbolAddress(&pUhi_, g_Uhi);
    cudaGetSymbolAddress(&pUlo_, g_Ulo);
    cudaGetSymbolAddress(&pMhi_, g_Mhi);
    cudaGetSymbolAddress(&pMlo_, g_Mlo);
    cudaGetSymbolAddress(&pWh_, g_Wth);
    cudaGetSymbolAddress(&pWl_, g_Wtl);
    cudaGetSymbolAddress(&pcK, g_cnt_knn);
    cudaGetSymbolAddress(&poK, g_off_knn);
    cudaGetSymbolAddress(&puK, g_cur_knn);
    cudaGetSymbolAddress(&psK, g_src_knn);
    cudaGetSymbolAddress(&piK, g_inv_knn);
    cudaGetSymbolAddress(&pcP, g_cnt_ppi);
    cudaGetSymbolAddress(&poP, g_off_ppi);
    cudaGetSymbolAddress(&puP, g_cur_ppi);
    cudaGetSymbolAddress(&psP, g_src_ppi);
    cudaGetSymbolAddress(&piP, g_inv_ppi);

    float* pT = (float*)pT_;
    float* pU = (float*)pU_;
    __nv_bfloat16* pThi = (__nv_bfloat16*)pThi_;
    __nv_bfloat16* pTlo = (__nv_bfloat16*)pTlo_;
    __nv_bfloat16* pUhi = (__nv_bfloat16*)pUhi_;
    __nv_bfloat16* pUlo = (__nv_bfloat16*)pUlo_;
    __nv_bfloat16* pMhi = (__nv_bfloat16*)pMhi_;
    __nv_bfloat16* pMlo = (__nv_bfloat16*)pMlo_;
    __nv_bfloat16* pWh = (__nv_bfloat16*)pWh_;
    __nv_bfloat16* pWl = (__nv_bfloat16*)pWl_;

    cudaFuncSetAttribute(gemm_mma_kernel<0>, cudaFuncAttributeMaxDynamicSharedMemorySize, G_SMEM);
    cudaFuncSetAttribute(gemm_mma_kernel<1>, cudaFuncAttributeMaxDynamicSharedMemorySize, G_SMEM);

    // ---- CSR build ----
    zero_counts_kernel<<<8, 256>>>();
    count_kernel<<<(EK + 255) / 256, 256>>>(knn_tgt, EK, (int*)pcK);
    count_kernel<<<(EP + 255) / 256, 256>>>(ppi_tgt, EP, (int*)pcP);
    scan_kernel<<<1, 1024>>>((int*)pcK, (int*)poK, (float*)piK, (int*)puK, NC);
    scan_kernel<<<1, 1024>>>((int*)pcP, (int*)poP, (float*)piP, (int*)puP, NG);
    fill_kernel<<<(EK + 255) / 256, 256>>>(knn_src, knn_tgt, EK, (int*)puK, (int*)psK);
    fill_kernel<<<(EP + 255) / 256, 256>>>(ppi_src, ppi_tgt, EP, (int*)puP, (int*)psP);
    sort_buckets_kernel<<<8, 256>>>((int*)poK, (int*)psK, NC);
    sort_buckets_kernel<<<8, 256>>>((int*)poP, (int*)psP, NG);

    // ---- weight prep: transpose + hi/lo split (16 matrices) ----
    dim3 wgrid(64, 64, 16), tblk(32, 8);
    wprep_kernel<<<wgrid, tblk>>>(col_Wl, col_Wr, row_Wl, row_Wr, pWh, pWl);

    // ---- input prep: x^T (cells x genes), fp32 + hi/lo ----
    dim3 tgrid(64, 64);
    transpose_conv_kernel<<<tgrid, tblk>>>(x, pT, pThi, pTlo);

    dim3 ggrid(16, 16);   // 128x128 tiles -> 256 CTAs, occ=2 per SM

    for (int i = 0; i < NL; ++i) {
        const __nv_bfloat16* cWlh = pWh + (long)(0 * 4 + i) * NN;
        const __nv_bfloat16* cWll = pWl + (long)(0 * 4 + i) * NN;
        const __nv_bfloat16* cWrh = pWh + (long)(1 * 4 + i) * NN;
        const __nv_bfloat16* cWrl = pWl + (long)(1 * 4 + i) * NN;
        const __nv_bfloat16* rWlh = pWh + (long)(2 * 4 + i) * NN;
        const __nv_bfloat16* rWll = pWl + (long)(2 * 4 + i) * NN;
        const __nv_bfloat16* rWrh = pWh + (long)(3 * 4 + i) * NN;
        const __nv_bfloat16* rWrl = pWl + (long)(3 * 4 + i) * NN;
        const float* cbl = col_bl + (long)i * 2048;
        const float* rbl = row_bl + (long)i * 2048;

        // cols side: operates on T = h^T [cells, genes]; writes U = Z_c^T [genes, cells]
        agg_conv_kernel<<<NC, 128>>>(pT, pMhi, pMlo, (int*)poK, (int*)psK, (float*)piK);
        gemm_mma_kernel<1><<<ggrid, 256, G_SMEM>>>(pMhi, pMlo, pThi, pTlo,
                                                   cWlh, cWll, cWrh, cWrl, cbl,
                                                   pU, pUhi, pUlo);

        // rows side: operates on U [genes, cells]; writes T = Z_r^T (or d_out, last layer)
        agg_conv_kernel<<<NG, 128>>>(pU, pMhi, pMlo, (int*)poP, (int*)psP, (float*)piP);
        if (i == NL - 1) {
            gemm_mma_kernel<0><<<ggrid, 256, G_SMEM>>>(pMhi, pMlo, pUhi, pUlo,
                                                       rWlh, rWll, rWrh, rWrl, rbl,
                                                       (float*)d_out, pThi, pTlo);
        } else {
            gemm_mma_kernel<1><<<ggrid, 256, G_SMEM>>>(pMhi, pMlo, pUhi, pUlo,
                                                       rWlh, rWll, rWrh, rWrl, rbl,
                                                       pT, pThi, pTlo);
        }
    }
}

// round 14
// speedup vs baseline: 1.1916x; 1.1916x over previous
#include <cuda_runtime.h>
#include <cuda_bf16.h>
#include <cstdint>

#define NG 2048      // genes
#define NC 2048      // cells
#define EK 30720
#define EP 65536
#define NL 4
#define NN (2048*2048)
#define NEG 0.01f

// ---------------- scratch (static device globals; no allocation) -------------
__device__ float g_T[NN];                 // fp32 activations, orientation A
__device__ __nv_bfloat16 g_Thi[NN];
__device__ __nv_bfloat16 g_Tlo[NN];
__device__ float g_U[NN];                 // fp32 activations, orientation B
__device__ __nv_bfloat16 g_Uhi[NN];
__device__ __nv_bfloat16 g_Ulo[NN];
__device__ __nv_bfloat16 g_Mhi[NN];      // mean operand hi/lo
__device__ __nv_bfloat16 g_Mlo[NN];
__device__ __nv_bfloat16 g_Wth[16ll*NN]; // 16 transposed weights, hi
__device__ __nv_bfloat16 g_Wtl[16ll*NN]; // 16 transposed weights, lo

__device__ int   g_cnt_knn[NC];
__device__ int   g_off_knn[NC + 1];
__device__ int   g_cur_knn[NC];
__device__ int   g_src_knn[EK];
__device__ float g_inv_knn[NC];

__device__ int   g_cnt_ppi[NG];
__device__ int   g_off_ppi[NG + 1];
__device__ int   g_cur_ppi[NG];
__device__ int   g_src_ppi[EP];
__device__ float g_inv_ppi[NG];

// ---------------- helpers ------------------------------------------------------
__device__ __forceinline__ uint32_t smem_u32(const void* p) {
    uint32_t a;
    asm("{ .reg .u64 t; cvta.to.shared.u64 t, %1; cvt.u32.u64 %0, t; }" : "=r"(a) : "l"(p));
    return a;
}
#define CP16(dst, src) \
    asm volatile("cp.async.cg.shared.global [%0], [%1], 16;\n" :: "r"(dst), "l"(src))

__device__ __forceinline__ void mma_bf16(float* c, const uint32_t* a, uint32_t b0, uint32_t b1) {
    asm volatile(
        "mma.sync.aligned.m16n8k16.row.col.f32.bf16.bf16.f32 "
        "{%0,%1,%2,%3}, {%4,%5,%6,%7}, {%8,%9}, {%0,%1,%2,%3};\n"
        : "+f"(c[0]), "+f"(c[1]), "+f"(c[2]), "+f"(c[3])
        : "r"(a[0]), "r"(a[1]), "r"(a[2]), "r"(a[3]), "r"(b0), "r"(b1));
}

// swizzled word index within a 128B-row tile: rows of 32 words, bits2-4 XORed by r
__device__ __forceinline__ int swidx(int r, int w) {
    return r * 32 + (w ^ ((r & 7) << 2));
}

// ---------------- setup kernels (CSR) ------------------------------------------
__global__ void zero_counts_kernel() {
    int t = blockIdx.x * blockDim.x + threadIdx.x;
    if (t < NC) g_cnt_knn[t] = 0;
    if (t < NG) g_cnt_ppi[t] = 0;
}
__global__ void count_kernel(const int* __restrict__ tgt, int E, int* __restrict__ cnt) {
    int e = blockIdx.x * blockDim.x + threadIdx.x;
    if (e < E) atomicAdd(&cnt[tgt[e]], 1);
}
__global__ void scan_kernel(const int* __restrict__ cnt, int* __restrict__ off,
                            float* __restrict__ inv, int* __restrict__ cur, int n) {
    __shared__ int s[1024];
    int t = threadIdx.x;
    int c0 = cnt[2 * t], c1 = cnt[2 * t + 1];
    s[t] = c0 + c1;
    __syncthreads();
    for (int d = 1; d < 1024; d <<= 1) {
        int v = (t >= d) ? s[t - d] : 0;
        __syncthreads();
        s[t] += v;
        __syncthreads();
    }
    int incl = s[t];
    int ex = incl - (c0 + c1);
    off[2 * t] = ex;       off[2 * t + 1] = ex + c0;
    cur[2 * t] = ex;       cur[2 * t + 1] = ex + c0;
    inv[2 * t]     = 1.0f / fmaxf((float)c0, 1.0f);
    inv[2 * t + 1] = 1.0f / fmaxf((float)c1, 1.0f);
    if (t == 1023) off[n] = incl;
}
__global__ void fill_kernel(const int* __restrict__ src, const int* __restrict__ tgt,
                            int E, int* __restrict__ cur, int* __restrict__ outsrc) {
    int e = blockIdx.x * blockDim.x + threadIdx.x;
    if (e < E) {
        int p = atomicAdd(&cur[tgt[e]], 1);
        outsrc[p] = src[e];
    }
}
__global__ void sort_buckets_kernel(const int* __restrict__ off, int* __restrict__ srcs, int n) {
    int t = blockIdx.x * blockDim.x + threadIdx.x;
    if (t >= n) return;
    int a = off[t], b = off[t + 1];
    int m = b - a;
    if (m <= 1 || m > 192) return;
    int buf[192];
    for (int i = 0; i < m; i++) buf[i] = srcs[a + i];
    for (int i = 1; i < m; i++) {
        int key = buf[i];
        int j = i - 1;
        while (j >= 0 && buf[j] > key) { buf[j + 1] = buf[j]; j--; }
        buf[j + 1] = key;
    }
    for (int i = 0; i < m; i++) srcs[a + i] = buf[i];
}

// ---------------- weight prep: transpose + bf16 hi/lo split --------------------
__global__ void wprep_kernel(const float* __restrict__ cWl, const float* __restrict__ cWr,
                             const float* __restrict__ rWl, const float* __restrict__ rWr,
                             __nv_bfloat16* __restrict__ wh, __nv_bfloat16* __restrict__ wl) {
    int z = blockIdx.z;
    const float* src;
    int t = z >> 2;
    if (t == 0) src = cWl; else if (t == 1) src = cWr; else if (t == 2) src = rWl; else src = rWr;
    src += (long)(z & 3) * NN;
    __nv_bfloat16* oh = wh + (long)z * NN;
    __nv_bfloat16* ol = wl + (long)z * NN;

    __shared__ float tile[32][33];
    int x = blockIdx.x * 32 + threadIdx.x;  // n
    int y = blockIdx.y * 32 + threadIdx.y;  // k
#pragma unroll
    for (int i = 0; i < 32; i += 8)
        tile[threadIdx.y + i][threadIdx.x] = src[(long)(y + i) * 2048 + x];
    __syncthreads();
    x = blockIdx.y * 32 + threadIdx.x;      // k
    y = blockIdx.x * 32 + threadIdx.y;      // n
#pragma unroll
    for (int i = 0; i < 32; i += 8) {
        float v = tile[threadIdx.x][threadIdx.y + i];
        long o = (long)(y + i) * 2048 + x;
        __nv_bfloat16 h = __float2bfloat16(v);
        oh[o] = h;
        ol[o] = __float2bfloat16(v - __bfloat162float(h));
    }
}

// ---------------- transpose + hi/lo convert (input x only) ---------------------
__global__ void transpose_conv_kernel(const float* __restrict__ in, float* __restrict__ outf,
                                      __nv_bfloat16* __restrict__ oh, __nv_bfloat16* __restrict__ ol) {
    __shared__ float tile[32][33];
    int x = blockIdx.x * 32 + threadIdx.x;
    int y = blockIdx.y * 32 + threadIdx.y;
#pragma unroll
    for (int i = 0; i < 32; i += 8)
        tile[threadIdx.y + i][threadIdx.x] = in[(long)(y + i) * 2048 + x];
    __syncthreads();
    x = blockIdx.y * 32 + threadIdx.x;
    y = blockIdx.x * 32 + threadIdx.y;
#pragma unroll
    for (int i = 0; i < 32; i += 8) {
        float v = tile[threadIdx.x][threadIdx.y + i];
        long o = (long)(y + i) * 2048 + x;
        outf[o] = v;
        __nv_bfloat16 h = __float2bfloat16(v);
        oh[o] = h;
        ol[o] = __float2bfloat16(v - __bfloat162float(h));
    }
}

// ---------------- segment mean + hi/lo convert ----------------------------------
__device__ __forceinline__ void st_hl(__nv_bfloat162* oh, __nv_bfloat162* ol,
                                      long i2, float x, float y) {
    __nv_bfloat16 hx = __float2bfloat16(x), hy = __float2bfloat16(y);
    oh[i2] = __halves2bfloat162(hx, hy);
    ol[i2] = __halves2bfloat162(__float2bfloat16(x - __bfloat162float(hx)),
                                __float2bfloat16(y - __bfloat162float(hy)));
}
__global__ void agg_conv_kernel(const float* __restrict__ in,
                                __nv_bfloat16* __restrict__ ohr, __nv_bfloat16* __restrict__ olr,
                                const int* __restrict__ off, const int* __restrict__ srcs,
                                const float* __restrict__ inv) {
    int r = blockIdx.x;
    int t = threadIdx.x;
    const float4* base = (const float4*)in;
    float4 a0 = make_float4(0.f, 0.f, 0.f, 0.f), a1 = a0, a2 = a0, a3 = a0;
    int s0 = off[r], s1 = off[r + 1];
    for (int j = s0; j < s1; j++) {
        const float4* row = base + (long)srcs[j] * 512;
        float4 v0 = row[t], v1 = row[t + 128], v2 = row[t + 256], v3 = row[t + 384];
        a0.x += v0.x; a0.y += v0.y; a0.z += v0.z; a0.w += v0.w;
        a1.x += v1.x; a1.y += v1.y; a1.z += v1.z; a1.w += v1.w;
        a2.x += v2.x; a2.y += v2.y; a2.z += v2.z; a2.w += v2.w;
        a3.x += v3.x; a3.y += v3.y; a3.z += v3.z; a3.w += v3.w;
    }
    float sc = inv[r];
    a0.x *= sc; a0.y *= sc; a0.z *= sc; a0.w *= sc;
    a1.x *= sc; a1.y *= sc; a1.z *= sc; a1.w *= sc;
    a2.x *= sc; a2.y *= sc; a2.z *= sc; a2.w *= sc;
    a3.x *= sc; a3.y *= sc; a3.z *= sc; a3.w *= sc;
    __nv_bfloat162* oh = (__nv_bfloat162*)ohr;
    __nv_bfloat162* ol = (__nv_bfloat162*)olr;
    long b2 = (long)r * 1024;
    st_hl(oh, ol, b2 + 2 * (t)       + 0, a0.x, a0.y); st_hl(oh, ol, b2 + 2 * (t)       + 1, a0.z, a0.w);
    st_hl(oh, ol, b2 + 2 * (t + 128) + 0, a1.x, a1.y); st_hl(oh, ol, b2 + 2 * (t + 128) + 1, a1.z, a1.w);
    st_hl(oh, ol, b2 + 2 * (t + 256) + 0, a2.x, a2.y); st_hl(oh, ol, b2 + 2 * (t + 256) + 1, a2.z, a2.w);
    st_hl(oh, ol, b2 + 2 * (t + 384) + 0, a3.x, a3.y); st_hl(oh, ol, b2 + 2 * (t + 384) + 1, a3.z, a3.w);
}

// ---------------- HMMA fused dual GEMM + bias + LeakyReLU ----------------------
// C[m,n] = sum_k A1[m,k]*B1t[n,k] + A2[m,k]*B2t[n,k] + bias[n], lrelu.
// bf16 hi/lo 3-term split, fp32 accum, mma.sync m16n8k16, scalar LDS feeds.
// CTA tile 128x256 (128 CTAs = one wave), BK=64 (halved barrier count vs BK=32),
// 8 warps (2x4 grid, warp tile 64x64), double-buffered cp.async with ONE
// __syncthreads per iteration; next-stage load issued BEFORE compute.
// Smem: 128B rows, XOR swizzle (word ^= (r&7)<<2 on bits2-4) => conflict-free
// fragment reads and cp.async writes, no padding. Stage 96KB, 2 stages 192KB.
// TRANS=1: epilogue stages C tile in smem [n][m], warp-cooperative coalesced
//          row writes of C^T fp32 + bf16 hi/lo.  TRANS=0: direct fp32 stores.
#define G_STAGE 98304
#define G_SMEM  (2 * G_STAGE)   // 196608; epilogue staging needs 135168 (fits)

template<int TRANS>
__global__ __launch_bounds__(256, 1)
void gemm_mma_kernel(const __nv_bfloat16* __restrict__ A1h, const __nv_bfloat16* __restrict__ A1l,
                     const __nv_bfloat16* __restrict__ A2h, const __nv_bfloat16* __restrict__ A2l,
                     const __nv_bfloat16* __restrict__ B1h, const __nv_bfloat16* __restrict__ B1l,
                     const __nv_bfloat16* __restrict__ B2h, const __nv_bfloat16* __restrict__ B2l,
                     const float* __restrict__ bias, float* __restrict__ Cf,
                     __nv_bfloat16* __restrict__ CThi, __nv_bfloat16* __restrict__ CTlo) {
    extern __shared__ __align__(16) char smem[];
    const uint32_t sbase = smem_u32(smem);
    const int tid = threadIdx.x;
    const int wid = tid >> 5, lane = tid & 31;
    const int wr = wid >> 2, wc = wid & 3;         // 2x4 warp grid -> 64x64 warp tile
    const int bm = blockIdx.y * 128, bn = blockIdx.x * 256;

    float acc[4][8][4];
#pragma unroll
    for (int i = 0; i < 4; i++)
#pragma unroll
        for (int j = 0; j < 8; j++)
#pragma unroll
            for (int q = 0; q < 4; q++) acc[i][j][q] = 0.f;

    auto load_stage = [&](int it) {
        const int pr = it >> 5, kc = it & 31;      // 64 iterations: 32 per operand pair
        const int k0 = kc * 64;
        const uint32_t st = sbase + (it & 1) * G_STAGE;
        const __nv_bfloat16* Ah = pr ? A2h : A1h;
        const __nv_bfloat16* Al = pr ? A2l : A1l;
        const __nv_bfloat16* Bh = pr ? B2h : B1h;
        const __nv_bfloat16* Bl = pr ? B2l : B1l;
        // A: 128 rows x 8 16B-chunks = 1024 granules (x2 hi/lo)
#pragma unroll
        for (int j = 0; j < 4; ++j) {
            int i = tid + j * 256;
            int r = i >> 3, c = i & 7;
            uint32_t so = st + (uint32_t)(r * 128 + ((c ^ (r & 7)) << 4));
            long ga = (long)(bm + r) * 2048 + k0 + c * 8;
            CP16(so,          Ah + ga);
            CP16(so + 16384,  Al + ga);
        }
        // B: 256 rows x 8 chunks = 2048 granules (x2 hi/lo)
#pragma unroll
        for (int j = 0; j < 8; ++j) {
            int i = tid + j * 256;
            int r = i >> 3, c = i & 7;
            uint32_t so = st + 32768 + (uint32_t)(r * 128 + ((c ^ (r & 7)) << 4));
            long gb = (long)(bn + r) * 2048 + k0 + c * 8;
            CP16(so,          Bh + gb);
            CP16(so + 32768,  Bl + gb);
        }
        asm volatile("cp.async.commit_group;\n" ::: "memory");
    };

    load_stage(0);
    asm volatile("cp.async.wait_group 0;\n" ::: "memory");
    __syncthreads();

    for (int it = 0; it < 64; ++it) {
        if (it + 1 < 64) load_stage(it + 1);   // other buffer; safe (synced last iter)

        const char* stp = smem + (it & 1) * G_STAGE;
        const uint32_t* SAh = (const uint32_t*)(stp);
        const uint32_t* SAl = (const uint32_t*)(stp + 16384);
        const uint32_t* SBh = (const uint32_t*)(stp + 32768);
        const uint32_t* SBl = (const uint32_t*)(stp + 65536);

#pragma unroll
        for (int ks = 0; ks < 4; ++ks) {
            const int kw = ks * 8 + (lane & 3);
            uint32_t ah[4][4], al[4][4];
#pragma unroll
            for (int mt = 0; mt < 4; ++mt) {
                const int r = wr * 64 + mt * 16 + (lane >> 2);
                ah[mt][0] = SAh[swidx(r, kw)];
                ah[mt][1] = SAh[swidx(r + 8, kw)];
                ah[mt][2] = SAh[swidx(r, kw + 4)];
                ah[mt][3] = SAh[swidx(r + 8, kw + 4)];
                al[mt][0] = SAl[swidx(r, kw)];
                al[mt][1] = SAl[swidx(r + 8, kw)];
                al[mt][2] = SAl[swidx(r, kw + 4)];
                al[mt][3] = SAl[swidx(r + 8, kw + 4)];
            }
#pragma unroll
            for (int nt = 0; nt < 8; ++nt) {
                const int n = wc * 64 + nt * 8 + (lane >> 2);
                const uint32_t bh0 = SBh[swidx(n, kw)];
                const uint32_t bh1 = SBh[swidx(n, kw + 4)];
                const uint32_t bl0 = SBl[swidx(n, kw)];
                const uint32_t bl1 = SBl[swidx(n, kw + 4)];
#pragma unroll
                for (int mt = 0; mt < 4; ++mt) {
                    mma_bf16(acc[mt][nt], ah[mt], bh0, bh1);
                    mma_bf16(acc[mt][nt], ah[mt], bl0, bl1);
                    mma_bf16(acc[mt][nt], al[mt], bh0, bh1);
                }
            }
        }

        if (it + 1 < 64) {
            asm volatile("cp.async.wait_group 0;\n" ::: "memory"); // next stage landed
        }
        __syncthreads();   // publish next stage; WAR-protect buffer (it+1)&1's peer
    }

    if (TRANS) {
        // stage bias+lrelu'd tile into smem as [n][m] (stride 132 words)
        float* sm = (float*)smem;
#pragma unroll
        for (int mt = 0; mt < 4; ++mt) {
            const int m = wr * 64 + mt * 16 + (lane >> 2);
#pragma unroll
            for (int nt = 0; nt < 8; ++nt) {
                const int n = wc * 64 + nt * 8 + 2 * (lane & 3);
                const float b0 = __ldg(bias + bn + n), b1 = __ldg(bias + bn + n + 1);
                float v0 = acc[mt][nt][0] + b0; v0 = (v0 > 0.f) ? v0 : NEG * v0;
                float v1 = acc[mt][nt][1] + b1; v1 = (v1 > 0.f) ? v1 : NEG * v1;
                float v2 = acc[mt][nt][2] + b0; v2 = (v2 > 0.f) ? v2 : NEG * v2;
                float v3 = acc[mt][nt][3] + b1; v3 = (v3 > 0.f) ? v3 : NEG * v3;
                sm[n * 132 + m]           = v0;
                sm[(n + 1) * 132 + m]     = v1;
                sm[n * 132 + m + 8]       = v2;
                sm[(n + 1) * 132 + m + 8] = v3;
            }
        }
        __syncthreads();
        // warp-cooperative coalesced write-out: warp owns rows wid, wid+8, ...
        for (int rr = wid; rr < 256; rr += 8) {
            const float* rowp = sm + rr * 132;
            const long gn = bn + rr;
            float4 v = *(const float4*)(rowp + lane * 4);
            *(float4*)(Cf + gn * 2048 + bm + lane * 4) = v;
            __nv_bfloat16 h0 = __float2bfloat16(v.x), h1 = __float2bfloat16(v.y);
            __nv_bfloat16 h2 = __float2bfloat16(v.z), h3 = __float2bfloat16(v.w);
            __nv_bfloat162 a01 = __halves2bfloat162(h0, h1);
            __nv_bfloat162 a23 = __halves2bfloat162(h2, h3);
            __nv_bfloat162 c01 = __halves2bfloat162(
                __float2bfloat16(v.x - __bfloat162float(h0)),
                __float2bfloat16(v.y - __bfloat162float(h1)));
            __nv_bfloat162 c23 = __halves2bfloat162(
                __float2bfloat16(v.z - __bfloat162float(h2)),
                __float2bfloat16(v.w - __bfloat162float(h3)));
            uint2 uh, ul;
            uh.x = *(uint32_t*)&a01; uh.y = *(uint32_t*)&a23;
            ul.x = *(uint32_t*)&c01; ul.y = *(uint32_t*)&c23;
            *(uint2*)(CThi + gn * 2048 + bm + lane * 4) = uh;
            *(uint2*)(CTlo + gn * 2048 + bm + lane * 4) = ul;
        }
    } else {
        // direct fp32 stores (final layer)
#pragma unroll
        for (int mt = 0; mt < 4; ++mt) {
            const int row = bm + wr * 64 + mt * 16 + (lane >> 2);
#pragma unroll
            for (int nt = 0; nt < 8; ++nt) {
                const int col = bn + wc * 64 + nt * 8 + (lane & 3) * 2;
                const float b0 = __ldg(bias + col), b1 = __ldg(bias + col + 1);
                float v0 = acc[mt][nt][0] + b0;
                float v1 = acc[mt][nt][1] + b1;
                float v2 = acc[mt][nt][2] + b0;
                float v3 = acc[mt][nt][3] + b1;
                float2 o0, o1;
                o0.x = (v0 > 0.f) ? v0 : NEG * v0;
                o0.y = (v1 > 0.f) ? v1 : NEG * v1;
                o1.x = (v2 > 0.f) ? v2 : NEG * v2;
                o1.y = (v3 > 0.f) ? v3 : NEG * v3;
                *(float2*)(Cf + (long)row * 2048 + col) = o0;
                *(float2*)(Cf + (long)(row + 8) * 2048 + col) = o1;
            }
        }
    }
}

// ---------------- launch -----------------------------------------------------
extern "C" void kernel_launch(void* const* d_in, const int* in_sizes, int n_in,
                              void* d_out, int out_size) {
    const float* x      = (const float*)d_in[0];
    const int*   knn    = (const int*)d_in[1];
    const int*   ppi    = (const int*)d_in[2];
    const float* col_Wl = (const float*)d_in[3];
    const float* col_bl = (const float*)d_in[4];
    const float* col_Wr = (const float*)d_in[5];
    const float* row_Wl = (const float*)d_in[6];
    const float* row_bl = (const float*)d_in[7];
    const float* row_Wr = (const float*)d_in[8];

    const int* knn_src = knn;
    const int* knn_tgt = knn + EK;
    const int* ppi_src = ppi;
    const int* ppi_tgt = ppi + EP;

    void *pT_, *pThi_, *pTlo_, *pU_, *pUhi_, *pUlo_, *pMhi_, *pMlo_, *pWh_, *pWl_;
    void *pcK, *poK, *puK, *psK, *piK;
    void *pcP, *poP, *puP, *psP, *piP;
    cudaGetSymbolAddress(&pT_, g_T);
    cudaGetSymbolAddress(&pThi_, g_Thi);
    cudaGetSymbolAddress(&pTlo_, g_Tlo);
    cudaGetSymbolAddress(&pU_, g_U);
    cudaGetSymbolAddress(&pUhi_, g_Uhi);
    cudaGetSymbolAddress(&pUlo_, g_Ulo);
    cudaGetSymbolAddress(&pMhi_, g_Mhi);
    cudaGetSymbolAddress(&pMlo_, g_Mlo);
    cudaGetSymbolAddress(&pWh_, g_Wth);
    cudaGetSymbolAddress(&pWl_, g_Wtl);
    cudaGetSymbolAddress(&pcK, g_cnt_knn);
    cudaGetSymbolAddress(&poK, g_off_knn);
    cudaGetSymbolAddress(&puK, g_cur_knn);
    cudaGetSymbolAddress(&psK, g_src_knn);
    cudaGetSymbolAddress(&piK, g_inv_knn);
    cudaGetSymbolAddress(&pcP, g_cnt_ppi);
    cudaGetSymbolAddress(&poP, g_off_ppi);
    cudaGetSymbolAddress(&puP, g_cur_ppi);
    cudaGetSymbolAddress(&psP, g_src_ppi);
    cudaGetSymbolAddress(&piP, g_inv_ppi);

    float* pT = (float*)pT_;
    float* pU = (float*)pU_;
    __nv_bfloat16* pThi = (__nv_bfloat16*)pThi_;
    __nv_bfloat16* pTlo = (__nv_bfloat16*)pTlo_;
    __nv_bfloat16* pUhi = (__nv_bfloat16*)pUhi_;
    __nv_bfloat16* pUlo = (__nv_bfloat16*)pUlo_;
    __nv_bfloat16* pMhi = (__nv_bfloat16*)pMhi_;
    __nv_bfloat16* pMlo = (__nv_bfloat16*)pMlo_;
    __nv_bfloat16* pWh = (__nv_bfloat16*)pWh_;
    __nv_bfloat16* pWl = (__nv_bfloat16*)pWl_;

    cudaFuncSetAttribute(gemm_mma_kernel<0>, cudaFuncAttributeMaxDynamicSharedMemorySize, G_SMEM);
    cudaFuncSetAttribute(gemm_mma_kernel<1>, cudaFuncAttributeMaxDynamicSharedMemorySize, G_SMEM);

    // ---- CSR build ----
    zero_counts_kernel<<<8, 256>>>();
    count_kernel<<<(EK + 255) / 256, 256>>>(knn_tgt, EK, (int*)pcK);
    count_kernel<<<(EP + 255) / 256, 256>>>(ppi_tgt, EP, (int*)pcP);
    scan_kernel<<<1, 1024>>>((int*)pcK, (int*)poK, (float*)piK, (int*)puK, NC);
    scan_kernel<<<1, 1024>>>((int*)pcP, (int*)poP, (float*)piP, (int*)puP, NG);
    fill_kernel<<<(EK + 255) / 256, 256>>>(knn_src, knn_tgt, EK, (int*)puK, (int*)psK);
    fill_kernel<<<(EP + 255) / 256, 256>>>(ppi_src, ppi_tgt, EP, (int*)puP, (int*)psP);
    sort_buckets_kernel<<<8, 256>>>((int*)poK, (int*)psK, NC);
    sort_buckets_kernel<<<8, 256>>>((int*)poP, (int*)psP, NG);

    // ---- weight prep: transpose + hi/lo split (16 matrices) ----
    dim3 wgrid(64, 64, 16), tblk(32, 8);
    wprep_kernel<<<wgrid, tblk>>>(col_Wl, col_Wr, row_Wl, row_Wr, pWh, pWl);

    // ---- input prep: x^T (cells x genes), fp32 + hi/lo ----
    dim3 tgrid(64, 64);
    transpose_conv_kernel<<<tgrid, tblk>>>(x, pT, pThi, pTlo);

    dim3 ggrid(8, 16);   // 128x256 tiles -> 128 CTAs = one full wave

    for (int i = 0; i < NL; ++i) {
        const __nv_bfloat16* cWlh = pWh + (long)(0 * 4 + i) * NN;
        const __nv_bfloat16* cWll = pWl + (long)(0 * 4 + i) * NN;
        const __nv_bfloat16* cWrh = pWh + (long)(1 * 4 + i) * NN;
        const __nv_bfloat16* cWrl = pWl + (long)(1 * 4 + i) * NN;
        const __nv_bfloat16* rWlh = pWh + (long)(2 * 4 + i) * NN;
        const __nv_bfloat16* rWll = pWl + (long)(2 * 4 + i) * NN;
        const __nv_bfloat16* rWrh = pWh + (long)(3 * 4 + i) * NN;
        const __nv_bfloat16* rWrl = pWl + (long)(3 * 4 + i) * NN;
        const float* cbl = col_bl + (long)i * 2048;
        const float* rbl = row_bl + (long)i * 2048;

        // cols side: operates on T = h^T [cells, genes]; writes U = Z_c^T [genes, cells]
        agg_conv_kernel<<<NC, 128>>>(pT, pMhi, pMlo, (int*)poK, (int*)psK, (float*)piK);
        gemm_mma_kernel<1><<<ggrid, 256, G_SMEM>>>(pMhi, pMlo, pThi, pTlo,
                                                   cWlh, cWll, cWrh, cWrl, cbl,
                                                   pU, pUhi, pUlo);

        // rows side: operates on U [genes, cells]; writes T = Z_r^T (or d_out, last layer)
        agg_conv_kernel<<<NG, 128>>>(pU, pMhi, pMlo, (int*)poP, (int*)psP, (float*)piP);
        if (i == NL - 1) {
            gemm_mma_kernel<0><<<ggrid, 256, G_SMEM>>>(pMhi, pMlo, pUhi, pUlo,
                                                       rWlh, rWll, rWrh, rWrl, rbl,
                                                       (float*)d_out, pThi, pTlo);
        } else {
            gemm_mma_kernel<1><<<ggrid, 256, G_SMEM>>>(pMhi, pMlo, pUhi, pUlo,
                                                       rWlh, rWll, rWrh, rWrl, rbl,
                                                       pT, pThi, pTlo);
        }
    }
}

// round 15
// speedup vs baseline: 1.2303x; 1.0325x over previous
#include <cuda_runtime.h>
#include <cuda_bf16.h>
#include <cstdint>

#define NG 2048      // genes
#define NC 2048      // cells
#define EK 30720
#define EP 65536
#define NL 4
#define NN (2048*2048)
#define NEG 0.01f

// ---------------- scratch (static device globals; no allocation) -------------
__device__ float g_T[NN];                 // fp32 activations, orientation A
__device__ __nv_bfloat16 g_Thi[NN];
__device__ __nv_bfloat16 g_Tlo[NN];
__device__ float g_U[NN];                 // fp32 activations, orientation B
__device__ __nv_bfloat16 g_Uhi[NN];
__device__ __nv_bfloat16 g_Ulo[NN];
__device__ __nv_bfloat16 g_Mhi[NN];      // mean operand hi/lo
__device__ __nv_bfloat16 g_Mlo[NN];
__device__ __nv_bfloat16 g_Wth[16ll*NN]; // 16 transposed weights, hi
__device__ __nv_bfloat16 g_Wtl[16ll*NN]; // 16 transposed weights, lo

__device__ int   g_cnt_knn[NC];
__device__ int   g_off_knn[NC + 1];
__device__ int   g_cur_knn[NC];
__device__ int   g_src_knn[EK];
__device__ float g_inv_knn[NC];

__device__ int   g_cnt_ppi[NG];
__device__ int   g_off_ppi[NG + 1];
__device__ int   g_cur_ppi[NG];
__device__ int   g_src_ppi[EP];
__device__ float g_inv_ppi[NG];

// ---------------- helpers ------------------------------------------------------
__device__ __forceinline__ uint32_t smem_u32(const void* p) {
    uint32_t a;
    asm("{ .reg .u64 t; cvta.to.shared.u64 t, %1; cvt.u32.u64 %0, t; }" : "=r"(a) : "l"(p));
    return a;
}
#define CP16(dst, src) \
    asm volatile("cp.async.cg.shared.global [%0], [%1], 16;\n" :: "r"(dst), "l"(src))

__device__ __forceinline__ void mma_bf16(float* c, const uint32_t* a, uint32_t b0, uint32_t b1) {
    asm volatile(
        "mma.sync.aligned.m16n8k16.row.col.f32.bf16.bf16.f32 "
        "{%0,%1,%2,%3}, {%4,%5,%6,%7}, {%8,%9}, {%0,%1,%2,%3};\n"
        : "+f"(c[0]), "+f"(c[1]), "+f"(c[2]), "+f"(c[3])
        : "r"(a[0]), "r"(a[1]), "r"(a[2]), "r"(a[3]), "r"(b0), "r"(b1));
}

// swizzled word index within a 128B-row tile: rows of 32 words, bits2-4 XORed by r
__device__ __forceinline__ int swidx(int r, int w) {
    return r * 32 + (w ^ ((r & 7) << 2));
}

// ---------------- setup kernels (CSR) ------------------------------------------
__global__ void zero_counts_kernel() {
    int t = blockIdx.x * blockDim.x + threadIdx.x;
    if (t < NC) g_cnt_knn[t] = 0;
    if (t < NG) g_cnt_ppi[t] = 0;
}
__global__ void count_kernel(const int* __restrict__ tgt, int E, int* __restrict__ cnt) {
    int e = blockIdx.x * blockDim.x + threadIdx.x;
    if (e < E) atomicAdd(&cnt[tgt[e]], 1);
}
__global__ void scan_kernel(const int* __restrict__ cnt, int* __restrict__ off,
                            float* __restrict__ inv, int* __restrict__ cur, int n) {
    __shared__ int s[1024];
    int t = threadIdx.x;
    int c0 = cnt[2 * t], c1 = cnt[2 * t + 1];
    s[t] = c0 + c1;
    __syncthreads();
    for (int d = 1; d < 1024; d <<= 1) {
        int v = (t >= d) ? s[t - d] : 0;
        __syncthreads();
        s[t] += v;
        __syncthreads();
    }
    int incl = s[t];
    int ex = incl - (c0 + c1);
    off[2 * t] = ex;       off[2 * t + 1] = ex + c0;
    cur[2 * t] = ex;       cur[2 * t + 1] = ex + c0;
    inv[2 * t]     = 1.0f / fmaxf((float)c0, 1.0f);
    inv[2 * t + 1] = 1.0f / fmaxf((float)c1, 1.0f);
    if (t == 1023) off[n] = incl;
}
__global__ void fill_kernel(const int* __restrict__ src, const int* __restrict__ tgt,
                            int E, int* __restrict__ cur, int* __restrict__ outsrc) {
    int e = blockIdx.x * blockDim.x + threadIdx.x;
    if (e < E) {
        int p = atomicAdd(&cur[tgt[e]], 1);
        outsrc[p] = src[e];
    }
}
__global__ void sort_buckets_kernel(const int* __restrict__ off, int* __restrict__ srcs, int n) {
    int t = blockIdx.x * blockDim.x + threadIdx.x;
    if (t >= n) return;
    int a = off[t], b = off[t + 1];
    int m = b - a;
    if (m <= 1 || m > 192) return;
    int buf[192];
    for (int i = 0; i < m; i++) buf[i] = srcs[a + i];
    for (int i = 1; i < m; i++) {
        int key = buf[i];
        int j = i - 1;
        while (j >= 0 && buf[j] > key) { buf[j + 1] = buf[j]; j--; }
        buf[j + 1] = key;
    }
    for (int i = 0; i < m; i++) srcs[a + i] = buf[i];
}

// ---------------- weight prep: transpose + bf16 hi/lo split --------------------
// store phase vectorized: each thread writes bf16x2 (2 consecutive k-cols)
__global__ void wprep_kernel(const float* __restrict__ cWl, const float* __restrict__ cWr,
                             const float* __restrict__ rWl, const float* __restrict__ rWr,
                             __nv_bfloat16* __restrict__ wh, __nv_bfloat16* __restrict__ wl) {
    int z = blockIdx.z;
    const float* src;
    int t = z >> 2;
    if (t == 0) src = cWl; else if (t == 1) src = cWr; else if (t == 2) src = rWl; else src = rWr;
    src += (long)(z & 3) * NN;
    __nv_bfloat16* oh = wh + (long)z * NN;
    __nv_bfloat16* ol = wl + (long)z * NN;

    __shared__ float tile[32][33];
    int x = blockIdx.x * 32 + threadIdx.x;  // n
    int y = blockIdx.y * 32 + threadIdx.y;  // k
#pragma unroll
    for (int i = 0; i < 32; i += 8)
        tile[threadIdx.y + i][threadIdx.x] = src[(long)(y + i) * 2048 + x];
    __syncthreads();
    // store: out[n][k] = src[k][n]; thread handles 2 consecutive k, 2 n-rows
    int lt = threadIdx.y * 32 + threadIdx.x;      // 0..255
    int k2 = (lt & 15) * 2;                        // k_local (even)
    int nl = lt >> 4;                              // 0..15
#pragma unroll
    for (int i = 0; i < 32; i += 16) {
        int n_local = nl + i;
        float v0 = tile[k2][n_local];
        float v1 = tile[k2 + 1][n_local];
        long o = (long)(blockIdx.x * 32 + n_local) * 2048 + blockIdx.y * 32 + k2;
        __nv_bfloat16 h0 = __float2bfloat16(v0);
        __nv_bfloat16 h1 = __float2bfloat16(v1);
        *(__nv_bfloat162*)(oh + o) = __halves2bfloat162(h0, h1);
        *(__nv_bfloat162*)(ol + o) = __halves2bfloat162(
            __float2bfloat16(v0 - __bfloat162float(h0)),
            __float2bfloat16(v1 - __bfloat162float(h1)));
    }
}

// ---------------- transpose + hi/lo convert (input x only) ---------------------
__global__ void transpose_conv_kernel(const float* __restrict__ in, float* __restrict__ outf,
                                      __nv_bfloat16* __restrict__ oh, __nv_bfloat16* __restrict__ ol) {
    __shared__ float tile[32][33];
    int x = blockIdx.x * 32 + threadIdx.x;
    int y = blockIdx.y * 32 + threadIdx.y;
#pragma unroll
    for (int i = 0; i < 32; i += 8)
        tile[threadIdx.y + i][threadIdx.x] = in[(long)(y + i) * 2048 + x];
    __syncthreads();
    x = blockIdx.y * 32 + threadIdx.x;
    y = blockIdx.x * 32 + threadIdx.y;
#pragma unroll
    for (int i = 0; i < 32; i += 8) {
        float v = tile[threadIdx.x][threadIdx.y + i];
        long o = (long)(y + i) * 2048 + x;
        outf[o] = v;
        __nv_bfloat16 h = __float2bfloat16(v);
        oh[o] = h;
        ol[o] = __float2bfloat16(v - __bfloat162float(h));
    }
}

// ---------------- segment mean + hi/lo convert ----------------------------------
__device__ __forceinline__ void st_hl(__nv_bfloat162* oh, __nv_bfloat162* ol,
                                      long i2, float x, float y) {
    __nv_bfloat16 hx = __float2bfloat16(x), hy = __float2bfloat16(y);
    oh[i2] = __halves2bfloat162(hx, hy);
    ol[i2] = __halves2bfloat162(__float2bfloat16(x - __bfloat162float(hx)),
                                __float2bfloat16(y - __bfloat162float(hy)));
}
__global__ void agg_conv_kernel(const float* __restrict__ in,
                                __nv_bfloat16* __restrict__ ohr, __nv_bfloat16* __restrict__ olr,
                                const int* __restrict__ off, const int* __restrict__ srcs,
                                const float* __restrict__ inv) {
    int r = blockIdx.x;
    int t = threadIdx.x;
    const float4* base = (const float4*)in;
    float4 a0 = make_float4(0.f, 0.f, 0.f, 0.f), a1 = a0, a2 = a0, a3 = a0;
    int s0 = off[r], s1 = off[r + 1];
    for (int j = s0; j < s1; j++) {
        const float4* row = base + (long)srcs[j] * 512;
        float4 v0 = row[t], v1 = row[t + 128], v2 = row[t + 256], v3 = row[t + 384];
        a0.x += v0.x; a0.y += v0.y; a0.z += v0.z; a0.w += v0.w;
        a1.x += v1.x; a1.y += v1.y; a1.z += v1.z; a1.w += v1.w;
        a2.x += v2.x; a2.y += v2.y; a2.z += v2.z; a2.w += v2.w;
        a3.x += v3.x; a3.y += v3.y; a3.z += v3.z; a3.w += v3.w;
    }
    float sc = inv[r];
    a0.x *= sc; a0.y *= sc; a0.z *= sc; a0.w *= sc;
    a1.x *= sc; a1.y *= sc; a1.z *= sc; a1.w *= sc;
    a2.x *= sc; a2.y *= sc; a2.z *= sc; a2.w *= sc;
    a3.x *= sc; a3.y *= sc; a3.z *= sc; a3.w *= sc;
    __nv_bfloat162* oh = (__nv_bfloat162*)ohr;
    __nv_bfloat162* ol = (__nv_bfloat162*)olr;
    long b2 = (long)r * 1024;
    st_hl(oh, ol, b2 + 2 * (t)       + 0, a0.x, a0.y); st_hl(oh, ol, b2 + 2 * (t)       + 1, a0.z, a0.w);
    st_hl(oh, ol, b2 + 2 * (t + 128) + 0, a1.x, a1.y); st_hl(oh, ol, b2 + 2 * (t + 128) + 1, a1.z, a1.w);
    st_hl(oh, ol, b2 + 2 * (t + 256) + 0, a2.x, a2.y); st_hl(oh, ol, b2 + 2 * (t + 256) + 1, a2.z, a2.w);
    st_hl(oh, ol, b2 + 2 * (t + 384) + 0, a3.x, a3.y); st_hl(oh, ol, b2 + 2 * (t + 384) + 1, a3.z, a3.w);
}

// ---------------- HMMA fused dual GEMM + bias + LeakyReLU ----------------------
// C[m,n] = sum_k A1[m,k]*B1t[n,k] + A2[m,k]*B2t[n,k] + bias[n], lrelu.
// bf16 hi/lo 3-term split, fp32 accum, mma.sync m16n8k16, scalar LDS feeds.
// CTA tile 128x256 (128 CTAs = one wave), BK=64, 8 warps (2x4 grid, 64x64 warp
// tile), double-buffered cp.async, ONE __syncthreads per iteration.
// KS-STAGGER: warps 0-3 process ks order 0,1,2,3; warps 4-7 order 2,3,0,1 so
// the two warps sharing an SMSP never stall on fragment-LDS bursts in phase.
// Smem: 128B rows, XOR swizzle => conflict-free, no padding. 2x96KB stages.
// TRANS=1: epilogue stages C tile in smem [n][m], warp-cooperative coalesced
//          row writes of C^T fp32 + bf16 hi/lo.  TRANS=0: direct fp32 stores.
#define G_STAGE 98304
#define G_SMEM  (2 * G_STAGE)   // 196608; epilogue staging needs 135168 (fits)

template<int TRANS>
__global__ __launch_bounds__(256, 1)
void gemm_mma_kernel(const __nv_bfloat16* __restrict__ A1h, const __nv_bfloat16* __restrict__ A1l,
                     const __nv_bfloat16* __restrict__ A2h, const __nv_bfloat16* __restrict__ A2l,
                     const __nv_bfloat16* __restrict__ B1h, const __nv_bfloat16* __restrict__ B1l,
                     const __nv_bfloat16* __restrict__ B2h, const __nv_bfloat16* __restrict__ B2l,
                     const float* __restrict__ bias, float* __restrict__ Cf,
                     __nv_bfloat16* __restrict__ CThi, __nv_bfloat16* __restrict__ CTlo) {
    extern __shared__ __align__(16) char smem[];
    const uint32_t sbase = smem_u32(smem);
    const int tid = threadIdx.x;
    const int wid = tid >> 5, lane = tid & 31;
    const int wr = wid >> 2, wc = wid & 3;         // 2x4 warp grid -> 64x64 warp tile
    const int krot = (wid >> 2) << 1;              // 0 for warps 0-3, 2 for warps 4-7
    const int bm = blockIdx.y * 128, bn = blockIdx.x * 256;

    float acc[4][8][4];
#pragma unroll
    for (int i = 0; i < 4; i++)
#pragma unroll
        for (int j = 0; j < 8; j++)
#pragma unroll
            for (int q = 0; q < 4; q++) acc[i][j][q] = 0.f;

    auto load_stage = [&](int it) {
        const int pr = it >> 5, kc = it & 31;      // 64 iterations: 32 per operand pair
        const int k0 = kc * 64;
        const uint32_t st = sbase + (it & 1) * G_STAGE;
        const __nv_bfloat16* Ah = pr ? A2h : A1h;
        const __nv_bfloat16* Al = pr ? A2l : A1l;
        const __nv_bfloat16* Bh = pr ? B2h : B1h;
        const __nv_bfloat16* Bl = pr ? B2l : B1l;
        // A: 128 rows x 8 16B-chunks = 1024 granules (x2 hi/lo)
#pragma unroll
        for (int j = 0; j < 4; ++j) {
            int i = tid + j * 256;
            int r = i >> 3, c = i & 7;
            uint32_t so = st + (uint32_t)(r * 128 + ((c ^ (r & 7)) << 4));
            long ga = (long)(bm + r) * 2048 + k0 + c * 8;
            CP16(so,          Ah + ga);
            CP16(so + 16384,  Al + ga);
        }
        // B: 256 rows x 8 chunks = 2048 granules (x2 hi/lo)
#pragma unroll
        for (int j = 0; j < 8; ++j) {
            int i = tid + j * 256;
            int r = i >> 3, c = i & 7;
            uint32_t so = st + 32768 + (uint32_t)(r * 128 + ((c ^ (r & 7)) << 4));
            long gb = (long)(bn + r) * 2048 + k0 + c * 8;
            CP16(so,          Bh + gb);
            CP16(so + 32768,  Bl + gb);
        }
        asm volatile("cp.async.commit_group;\n" ::: "memory");
    };

    load_stage(0);
    asm volatile("cp.async.wait_group 0;\n" ::: "memory");
    __syncthreads();

    for (int it = 0; it < 64; ++it) {
        if (it + 1 < 64) load_stage(it + 1);   // other buffer; safe (synced last iter)

        const char* stp = smem + (it & 1) * G_STAGE;
        const uint32_t* SAh = (const uint32_t*)(stp);
        const uint32_t* SAl = (const uint32_t*)(stp + 16384);
        const uint32_t* SBh = (const uint32_t*)(stp + 32768);
        const uint32_t* SBl = (const uint32_t*)(stp + 65536);

#pragma unroll
        for (int ks_i = 0; ks_i < 4; ++ks_i) {
            const int ks = (ks_i + krot) & 3;      // stagger across SMSP-paired warps
            const int kw = ks * 8 + (lane & 3);
            uint32_t ah[4][4], al[4][4];
#pragma unroll
            for (int mt = 0; mt < 4; ++mt) {
                const int r = wr * 64 + mt * 16 + (lane >> 2);
                ah[mt][0] = SAh[swidx(r, kw)];
                ah[mt][1] = SAh[swidx(r + 8, kw)];
                ah[mt][2] = SAh[swidx(r, kw + 4)];
                ah[mt][3] = SAh[swidx(r + 8, kw + 4)];
                al[mt][0] = SAl[swidx(r, kw)];
                al[mt][1] = SAl[swidx(r + 8, kw)];
                al[mt][2] = SAl[swidx(r, kw + 4)];
                al[mt][3] = SAl[swidx(r + 8, kw + 4)];
            }
#pragma unroll
            for (int nt = 0; nt < 8; ++nt) {
                const int n = wc * 64 + nt * 8 + (lane >> 2);
                const uint32_t bh0 = SBh[swidx(n, kw)];
                const uint32_t bh1 = SBh[swidx(n, kw + 4)];
                const uint32_t bl0 = SBl[swidx(n, kw)];
                const uint32_t bl1 = SBl[swidx(n, kw + 4)];
#pragma unroll
                for (int mt = 0; mt < 4; ++mt) {
                    mma_bf16(acc[mt][nt], ah[mt], bh0, bh1);
                    mma_bf16(acc[mt][nt], ah[mt], bl0, bl1);
                    mma_bf16(acc[mt][nt], al[mt], bh0, bh1);
                }
            }
        }

        if (it + 1 < 64) {
            asm volatile("cp.async.wait_group 0;\n" ::: "memory"); // next stage landed
        }
        __syncthreads();   // publish next stage; WAR-protect the buffer
    }

    if (TRANS) {
        // stage bias+lrelu'd tile into smem as [n][m] (stride 132 words)
        float* sm = (float*)smem;
#pragma unroll
        for (int mt = 0; mt < 4; ++mt) {
            const int m = wr * 64 + mt * 16 + (lane >> 2);
#pragma unroll
            for (int nt = 0; nt < 8; ++nt) {
                const int n = wc * 64 + nt * 8 + 2 * (lane & 3);
                const float b0 = __ldg(bias + bn + n), b1 = __ldg(bias + bn + n + 1);
                float v0 = acc[mt][nt][0] + b0; v0 = (v0 > 0.f) ? v0 : NEG * v0;
                float v1 = acc[mt][nt][1] + b1; v1 = (v1 > 0.f) ? v1 : NEG * v1;
                float v2 = acc[mt][nt][2] + b0; v2 = (v2 > 0.f) ? v2 : NEG * v2;
                float v3 = acc[mt][nt][3] + b1; v3 = (v3 > 0.f) ? v3 : NEG * v3;
                sm[n * 132 + m]           = v0;
                sm[(n + 1) * 132 + m]     = v1;
                sm[n * 132 + m + 8]       = v2;
                sm[(n + 1) * 132 + m + 8] = v3;
            }
        }
        __syncthreads();
        // warp-cooperative coalesced write-out: warp owns rows wid, wid+8, ...
        for (int rr = wid; rr < 256; rr += 8) {
            const float* rowp = sm + rr * 132;
            const long gn = bn + rr;
            float4 v = *(const float4*)(rowp + lane * 4);
            *(float4*)(Cf + gn * 2048 + bm + lane * 4) = v;
            __nv_bfloat16 h0 = __float2bfloat16(v.x), h1 = __float2bfloat16(v.y);
            __nv_bfloat16 h2 = __float2bfloat16(v.z), h3 = __float2bfloat16(v.w);
            __nv_bfloat162 a01 = __halves2bfloat162(h0, h1);
            __nv_bfloat162 a23 = __halves2bfloat162(h2, h3);
            __nv_bfloat162 c01 = __halves2bfloat162(
                __float2bfloat16(v.x - __bfloat162float(h0)),
                __float2bfloat16(v.y - __bfloat162float(h1)));
            __nv_bfloat162 c23 = __halves2bfloat162(
                __float2bfloat16(v.z - __bfloat162float(h2)),
                __float2bfloat16(v.w - __bfloat162float(h3)));
            uint2 uh, ul;
            uh.x = *(uint32_t*)&a01; uh.y = *(uint32_t*)&a23;
            ul.x = *(uint32_t*)&c01; ul.y = *(uint32_t*)&c23;
            *(uint2*)(CThi + gn * 2048 + bm + lane * 4) = uh;
            *(uint2*)(CTlo + gn * 2048 + bm + lane * 4) = ul;
        }
    } else {
        // direct fp32 stores (final layer)
#pragma unroll
        for (int mt = 0; mt < 4; ++mt) {
            const int row = bm + wr * 64 + mt * 16 + (lane >> 2);
#pragma unroll
            for (int nt = 0; nt < 8; ++nt) {
                const int col = bn + wc * 64 + nt * 8 + (lane & 3) * 2;
                const float b0 = __ldg(bias + col), b1 = __ldg(bias + col + 1);
                float v0 = acc[mt][nt][0] + b0;
                float v1 = acc[mt][nt][1] + b1;
                float v2 = acc[mt][nt][2] + b0;
                float v3 = acc[mt][nt][3] + b1;
                float2 o0, o1;
                o0.x = (v0 > 0.f) ? v0 : NEG * v0;
                o0.y = (v1 > 0.f) ? v1 : NEG * v1;
                o1.x = (v2 > 0.f) ? v2 : NEG * v2;
                o1.y = (v3 > 0.f) ? v3 : NEG * v3;
                *(float2*)(Cf + (long)row * 2048 + col) = o0;
                *(float2*)(Cf + (long)(row + 8) * 2048 + col) = o1;
            }
        }
    }
}

// ---------------- launch -----------------------------------------------------
extern "C" void kernel_launch(void* const* d_in, const int* in_sizes, int n_in,
                              void* d_out, int out_size) {
    const float* x      = (const float*)d_in[0];
    const int*   knn    = (const int*)d_in[1];
    const int*   ppi    = (const int*)d_in[2];
    const float* col_Wl = (const float*)d_in[3];
    const float* col_bl = (const float*)d_in[4];
    const float* col_Wr = (const float*)d_in[5];
    const float* row_Wl = (const float*)d_in[6];
    const float* row_bl = (const float*)d_in[7];
    const float* row_Wr = (const float*)d_in[8];

    const int* knn_src = knn;
    const int* knn_tgt = knn + EK;
    const int* ppi_src = ppi;
    const int* ppi_tgt = ppi + EP;

    void *pT_, *pThi_, *pTlo_, *pU_, *pUhi_, *pUlo_, *pMhi_, *pMlo_, *pWh_, *pWl_;
    void *pcK, *poK, *puK, *psK, *piK;
    void *pcP, *poP, *puP, *psP, *piP;
    cudaGetSymbolAddress(&pT_, g_T);
    cudaGetSymbolAddress(&pThi_, g_Thi);
    cudaGetSymbolAddress(&pTlo_, g_Tlo);
    cudaGetSymbolAddress(&pU_, g_U);
    cudaGetSymbolAddress(&pUhi_, g_Uhi);
    cudaGetSymbolAddress(&pUlo_, g_Ulo);
    cudaGetSymbolAddress(&pMhi_, g_Mhi);
    cudaGetSymbolAddress(&pMlo_, g_Mlo);
    cudaGetSymbolAddress(&pWh_, g_Wth);
    cudaGetSymbolAddress(&pWl_, g_Wtl);
    cudaGetSymbolAddress(&pcK, g_cnt_knn);
    cudaGetSymbolAddress(&poK, g_off_knn);
    cudaGetSymbolAddress(&puK, g_cur_knn);
    cudaGetSymbolAddress(&psK, g_src_knn);
    cudaGetSymbolAddress(&piK, g_inv_knn);
    cudaGetSymbolAddress(&pcP, g_cnt_ppi);
    cudaGetSymbolAddress(&poP, g_off_ppi);
    cudaGetSymbolAddress(&puP, g_cur_ppi);
    cudaGetSymbolAddress(&psP, g_src_ppi);
    cudaGetSymbolAddress(&piP, g_inv_ppi);

    float* pT = (float*)pT_;
    float* pU = (float*)pU_;
    __nv_bfloat16* pThi = (__nv_bfloat16*)pThi_;
    __nv_bfloat16* pTlo = (__nv_bfloat16*)pTlo_;
    __nv_bfloat16* pUhi = (__nv_bfloat16*)pUhi_;
    __nv_bfloat16* pUlo = (__nv_bfloat16*)pUlo_;
    __nv_bfloat16* pMhi = (__nv_bfloat16*)pMhi_;
    __nv_bfloat16* pMlo = (__nv_bfloat16*)pMlo_;
    __nv_bfloat16* pWh = (__nv_bfloat16*)pWh_;
    __nv_bfloat16* pWl = (__nv_bfloat16*)pWl_;

    cudaFuncSetAttribute(gemm_mma_kernel<0>, cudaFuncAttributeMaxDynamicSharedMemorySize, G_SMEM);
    cudaFuncSetAttribute(gemm_mma_kernel<1>, cudaFuncAttributeMaxDynamicSharedMemorySize, G_SMEM);

    // ---- CSR build ----
    zero_counts_kernel<<<8, 256>>>();
    count_kernel<<<(EK + 255) / 256, 256>>>(knn_tgt, EK, (int*)pcK);
    count_kernel<<<(EP + 255) / 256, 256>>>(ppi_tgt, EP, (int*)pcP);
    scan_kernel<<<1, 1024>>>((int*)pcK, (int*)poK, (float*)piK, (int*)puK, NC);
    scan_kernel<<<1, 1024>>>((int*)pcP, (int*)poP, (float*)piP, (int*)puP, NG);
    fill_kernel<<<(EK + 255) / 256, 256>>>(knn_src, knn_tgt, EK, (int*)puK, (int*)psK);
    fill_kernel<<<(EP + 255) / 256, 256>>>(ppi_src, ppi_tgt, EP, (int*)puP, (int*)psP);
    sort_buckets_kernel<<<8, 256>>>((int*)poK, (int*)psK, NC);
    sort_buckets_kernel<<<8, 256>>>((int*)poP, (int*)psP, NG);

    // ---- weight prep: transpose + hi/lo split (16 matrices) ----
    dim3 wgrid(64, 64, 16), tblk(32, 8);
    wprep_kernel<<<wgrid, tblk>>>(col_Wl, col_Wr, row_Wl, row_Wr, pWh, pWl);

    // ---- input prep: x^T (cells x genes), fp32 + hi/lo ----
    dim3 tgrid(64, 64);
    transpose_conv_kernel<<<tgrid, tblk>>>(x, pT, pThi, pTlo);

    dim3 ggrid(8, 16);   // 128x256 tiles -> 128 CTAs = one full wave

    for (int i = 0; i < NL; ++i) {
        const __nv_bfloat16* cWlh = pWh + (long)(0 * 4 + i) * NN;
        const __nv_bfloat16* cWll = pWl + (long)(0 * 4 + i) * NN;
        const __nv_bfloat16* cWrh = pWh + (long)(1 * 4 + i) * NN;
        const __nv_bfloat16* cWrl = pWl + (long)(1 * 4 + i) * NN;
        const __nv_bfloat16* rWlh = pWh + (long)(2 * 4 + i) * NN;
        const __nv_bfloat16* rWll = pWl + (long)(2 * 4 + i) * NN;
        const __nv_bfloat16* rWrh = pWh + (long)(3 * 4 + i) * NN;
        const __nv_bfloat16* rWrl = pWl + (long)(3 * 4 + i) * NN;
        const float* cbl = col_bl + (long)i * 2048;
        const float* rbl = row_bl + (long)i * 2048;

        // cols side: operates on T = h^T [cells, genes]; writes U = Z_c^T [genes, cells]
        agg_conv_kernel<<<NC, 128>>>(pT, pMhi, pMlo, (int*)poK, (int*)psK, (float*)piK);
        gemm_mma_kernel<1><<<ggrid, 256, G_SMEM>>>(pMhi, pMlo, pThi, pTlo,
                                                   cWlh, cWll, cWrh, cWrl, cbl,
                                                   pU, pUhi, pUlo);

        // rows side: operates on U [genes, cells]; writes T = Z_r^T (or d_out, last layer)
        agg_conv_kernel<<<NG, 128>>>(pU, pMhi, pMlo, (int*)poP, (int*)psP, (float*)piP);
        if (i == NL - 1) {
            gemm_mma_kernel<0><<<ggrid, 256, G_SMEM>>>(pMhi, pMlo, pUhi, pUlo,
                                                       rWlh, rWll, rWrh, rWrl, rbl,
                                                       (float*)d_out, pThi, pTlo);
        } else {
            gemm_mma_kernel<1><<<ggrid, 256, G_SMEM>>>(pMhi, pMlo, pUhi, pUlo,
                                                       rWlh, rWll, rWrh, rWrl, rbl,
                                                       pT, pThi, pTlo);
        }
    }
}